// round 16
// baseline (speedup 1.0000x reference)
#include <cuda_runtime.h>
#include <cuda_bf16.h>
#include <stdint.h>
#include <math.h>

#define NB 32
#define TT 1024
#define CC 512
#define KK 64
#define FEPS 1e-12f

#define STRB 144      // 64-col operand row stride bytes (36 words == 4 mod 32)
#define STRB2 272     // 128-col operand row stride bytes (68 words == 4 mod 32)

// kA smem (bytes) — R4 mainloop layout
#define A_XH 0                // 128 x 144 = 18432
#define A_XL 18432            // ends 36864
#define A_WH0 36864           // 64 x 144 = 9216
#define A_WL0 46080
#define A_WH1 55296
#define A_WL1 64512           // ends 73728
#define A_AUX 73728
#define SMEM_A 73984
// kA epilogue overlay (post-mainloop-sync reuse)
#define E_TH 0                // a hi bf16 [128 t][144B]
#define E_TL 18432            // a lo
#define E_RM 36864            // rowmax [2][128] f32
#define E_RS 37888            // rowsum [2][128] f32
#define E_PART 38912          // asum partials [4][64] f32

// kB smem — R10 layout (a [t][k])
#define B_XH 0                // 64 x 272 = 17408
#define B_XL 17408            // ends 34816
#define B_AH0 34816           // 64 x 144 = 9216
#define B_AL0 44032
#define B_AH1 53248
#define B_AL1 62464           // ends 71680
#define B_AUX 71680
#define SMEM_B 71936
#define O_SC 0                // 64 x 132 f32
#define O_SO 33792            // ends 67584

// ---- scratch ----
__device__ __align__(16) __nv_bfloat16 g_aTh[(size_t)NB * TT * KK];  // [n][t][k] hi
__device__ __align__(16) __nv_bfloat16 g_aTl[(size_t)NB * TT * KK];  // [n][t][k] lo
__device__ __align__(16) __nv_bfloat16 g_Wh[KK * CC];
__device__ __align__(16) __nv_bfloat16 g_Wl[KK * CC];
__device__ float g_asumP[NB * 8 * KK];
__device__ float g_sqP[NB * 4 * KK];

__device__ __forceinline__ uint32_t smem_u32(const void* p) {
    uint32_t a;
    asm("{ .reg .u64 t; cvta.to.shared.u64 t, %1; cvt.u32.u64 %0, t; }" : "=r"(a) : "l"(p));
    return a;
}
__device__ __forceinline__ uint32_t b2u(__nv_bfloat162 v) { return *reinterpret_cast<uint32_t*>(&v); }
__device__ __forceinline__ void split_pair(float f0, float f1, __nv_bfloat162& h, __nv_bfloat162& l) {
    h = __floats2bfloat162_rn(f0, f1);
    float2 hf = __bfloat1622float2(h);
    l = __floats2bfloat162_rn(f0 - hf.x, f1 - hf.y);
}
__device__ __forceinline__ void mma16816(float* d, const uint32_t* a, const uint32_t* b) {
    asm volatile("mma.sync.aligned.m16n8k16.row.col.f32.bf16.bf16.f32 "
                 "{%0,%1,%2,%3}, {%4,%5,%6,%7}, {%8,%9}, {%0,%1,%2,%3};"
                 : "+f"(d[0]), "+f"(d[1]), "+f"(d[2]), "+f"(d[3])
                 : "r"(a[0]), "r"(a[1]), "r"(a[2]), "r"(a[3]), "r"(b[0]), "r"(b[1]));
}
__device__ __forceinline__ void ldm4(uint32_t* r, uint32_t a) {
    asm volatile("ldmatrix.sync.aligned.m8n8.x4.shared.b16 {%0,%1,%2,%3}, [%4];"
                 : "=r"(r[0]), "=r"(r[1]), "=r"(r[2]), "=r"(r[3]) : "r"(a));
}
__device__ __forceinline__ void ldm4t(uint32_t* r, uint32_t a) {
    asm volatile("ldmatrix.sync.aligned.m8n8.x4.trans.shared.b16 {%0,%1,%2,%3}, [%4];"
                 : "=r"(r[0]), "=r"(r[1]), "=r"(r[2]), "=r"(r[3]) : "r"(a));
}
#define CPA16(dst, src) asm volatile("cp.async.ca.shared.global [%0], [%1], 16;" :: "r"(dst), "l"(src))
#define CPA_COMMIT() asm volatile("cp.async.commit_group;")
#define CPA_WAIT1() asm volatile("cp.async.wait_group 1;")
#define CPA_WAIT0() asm volatile("cp.async.wait_group 0;")

// ---------------------------------------------------------------------------
// kW: split W fp32 -> bf16 hi/lo, float4-vectorized, 64 CTAs for latency hiding
// ---------------------------------------------------------------------------
__global__ void kW(const float* __restrict__ W) {
    int i4 = blockIdx.x * 128 + threadIdx.x;     // float4 index, 8192 total
    if (i4 < KK * CC / 4) {
        float4 v = *(const float4*)&W[i4 * 4];
        __nv_bfloat162 h0, l0, h1, l1;
        split_pair(v.x, v.y, h0, l0);
        split_pair(v.z, v.w, h1, l1);
        *(uint2*)&g_Wh[i4 * 4] = make_uint2(b2u(h0), b2u(h1));
        *(uint2*)&g_Wl[i4 * 4] = make_uint2(b2u(l0), b2u(l1));
    }
}

// ---------------------------------------------------------------------------
// kA: logits[128t x 64k] = x @ W^T + bias, softmax -> a bf16 [n][t][k]
// R4 mainloop + register-resident epilogue. grid (8, 32), 256 thr. (R10 exact)
// ---------------------------------------------------------------------------
__global__ __launch_bounds__(256, 2) void kA(const float* __restrict__ x,
                                             const float* __restrict__ b) {
    extern __shared__ __align__(16) char sm[];
    const int tid = threadIdx.x, wid = tid >> 5, lane = tid & 31;
    const int n = blockIdx.y, tile = blockIdx.x, t0 = tile * 128;
    const int wt = (wid & 3) * 32, wk = (wid >> 2) * 32;
    const uint32_t sbase = smem_u32(sm);
    float* sAux = (float*)(sm + A_AUX);
    if (tid < KK) sAux[tid] = b[tid];

    float d[2][4][4];
#pragma unroll
    for (int mt = 0; mt < 2; mt++)
#pragma unroll
        for (int nt = 0; nt < 4; nt++)
#pragma unroll
            for (int j = 0; j < 4; j++) d[mt][nt][j] = 0.f;

    const float* xn = x + ((size_t)n * TT + t0) * CC;
    const int xt = tid >> 4, xc4 = tid & 15;
    const int wk8 = tid >> 3, wseg = tid & 7;

    float4 px[8];
#pragma unroll
    for (int it = 0; it < 8; it++)
        px[it] = *(const float4*)(xn + (size_t)(xt + it * 16) * CC + xc4 * 4);
    {   // W(0)
        uint32_t dh = sbase + A_WH0 + wk8 * STRB + wseg * 16;
#pragma unroll
        for (int q2 = 0; q2 < 2; q2++) {
            int k = wk8 + q2 * 32;
            CPA16(dh + q2 * 32 * STRB, &g_Wh[k * CC + wseg * 8]);
            CPA16(dh + q2 * 32 * STRB + 9216, &g_Wl[k * CC + wseg * 8]);
        }
        CPA_COMMIT();
    }

#pragma unroll 1
    for (int ch = 0; ch < 8; ch++) {
        __syncthreads();
#pragma unroll
        for (int it = 0; it < 8; it++) {
            __nv_bfloat162 h0, l0, h1, l1;
            split_pair(px[it].x, px[it].y, h0, l0);
            split_pair(px[it].z, px[it].w, h1, l1);
            uint32_t off = (uint32_t)((xt + it * 16) * STRB + xc4 * 8);
            *(uint2*)(sm + A_XH + off) = make_uint2(b2u(h0), b2u(h1));
            *(uint2*)(sm + A_XL + off) = make_uint2(b2u(l0), b2u(l1));
        }
        if (ch < 7) {
            uint32_t wb = ((ch + 1) & 1) ? A_WH1 : A_WH0;
            uint32_t dh = sbase + wb + wk8 * STRB + wseg * 16;
            int cn = (ch + 1) * 64;
#pragma unroll
            for (int q2 = 0; q2 < 2; q2++) {
                int k = wk8 + q2 * 32;
                CPA16(dh + q2 * 32 * STRB, &g_Wh[k * CC + cn + wseg * 8]);
                CPA16(dh + q2 * 32 * STRB + 9216, &g_Wl[k * CC + cn + wseg * 8]);
            }
            CPA_COMMIT();
#pragma unroll
            for (int it = 0; it < 8; it++)
                px[it] = *(const float4*)(xn + (size_t)(xt + it * 16) * CC + cn + xc4 * 4);
            CPA_WAIT1();
        } else {
            CPA_WAIT0();
        }
        __syncthreads();

        const uint32_t wbase = sbase + ((ch & 1) ? A_WH1 : A_WH0);
#pragma unroll
        for (int ks = 0; ks < 4; ks++) {
            const int cs = ks * 16;
            uint32_t ah[2][4], al[2][4];
#pragma unroll
            for (int mt = 0; mt < 2; mt++) {
                uint32_t a = sbase + A_XH + (uint32_t)((wt + mt * 16 + (lane & 15)) * STRB
                              + (cs + ((lane >> 4) << 3)) * 2);
                ldm4(ah[mt], a);
                ldm4(al[mt], a + 18432);
            }
            uint32_t bh[4][2], bl[4][2];
#pragma unroll
            for (int p = 0; p < 2; p++) {
                int g = lane >> 3;
                uint32_t a = wbase + (uint32_t)((wk + p * 16 + ((g >> 1) << 3) + (lane & 7)) * STRB
                              + (cs + ((g & 1) << 3)) * 2);
                uint32_t r[4];
                ldm4(r, a);
                bh[2 * p][0] = r[0]; bh[2 * p][1] = r[1];
                bh[2 * p + 1][0] = r[2]; bh[2 * p + 1][1] = r[3];
                ldm4(r, a + 9216);
                bl[2 * p][0] = r[0]; bl[2 * p][1] = r[1];
                bl[2 * p + 1][0] = r[2]; bl[2 * p + 1][1] = r[3];
            }
#pragma unroll
            for (int mt = 0; mt < 2; mt++)
#pragma unroll
                for (int nt = 0; nt < 4; nt++) {
                    mma16816(d[mt][nt], ah[mt], bh[nt]);
                    mma16816(d[mt][nt], ah[mt], bl[nt]);
                    mma16816(d[mt][nt], al[mt], bh[nt]);
                }
        }
    }
    __syncthreads();

    // ===== register-resident epilogue =====
    const int ra = lane >> 2, q = lane & 3, cb2 = q * 2;
    const int wtg = wid & 3, wkg = wid >> 2;
    float* rowmax = (float*)(sm + E_RM);
    float* rowsum = (float*)(sm + E_RS);
    float* sPart  = (float*)(sm + E_PART);

    float2 bb[4];
#pragma unroll
    for (int nt = 0; nt < 4; nt++) bb[nt] = *(float2*)&sAux[wk + nt * 8 + cb2];
#pragma unroll
    for (int mt = 0; mt < 2; mt++)
#pragma unroll
        for (int nt = 0; nt < 4; nt++) {
            d[mt][nt][0] += bb[nt].x; d[mt][nt][1] += bb[nt].y;
            d[mt][nt][2] += bb[nt].x; d[mt][nt][3] += bb[nt].y;
        }

    float m[2][2];
#pragma unroll
    for (int mt = 0; mt < 2; mt++) {
        m[mt][0] = -1e30f; m[mt][1] = -1e30f;
#pragma unroll
        for (int nt = 0; nt < 4; nt++) {
            m[mt][0] = fmaxf(m[mt][0], fmaxf(d[mt][nt][0], d[mt][nt][1]));
            m[mt][1] = fmaxf(m[mt][1], fmaxf(d[mt][nt][2], d[mt][nt][3]));
        }
    }
#pragma unroll
    for (int o = 1; o < 4; o <<= 1)
#pragma unroll
        for (int mt = 0; mt < 2; mt++)
#pragma unroll
            for (int rj = 0; rj < 2; rj++)
                m[mt][rj] = fmaxf(m[mt][rj], __shfl_xor_sync(0xffffffffu, m[mt][rj], o));
    if (q == 0) {
#pragma unroll
        for (int mt = 0; mt < 2; mt++)
#pragma unroll
            for (int rj = 0; rj < 2; rj++)
                rowmax[wkg * 128 + wt + mt * 16 + rj * 8 + ra] = m[mt][rj];
    }
    __syncthreads();
#pragma unroll
    for (int mt = 0; mt < 2; mt++)
#pragma unroll
        for (int rj = 0; rj < 2; rj++)
            m[mt][rj] = fmaxf(m[mt][rj], rowmax[(wkg ^ 1) * 128 + wt + mt * 16 + rj * 8 + ra]);

    float s[2][2] = {{0.f, 0.f}, {0.f, 0.f}};
#pragma unroll
    for (int mt = 0; mt < 2; mt++)
#pragma unroll
        for (int nt = 0; nt < 4; nt++) {
            float e0 = __expf(d[mt][nt][0] - m[mt][0]); d[mt][nt][0] = e0; s[mt][0] += e0;
            float e1 = __expf(d[mt][nt][1] - m[mt][0]); d[mt][nt][1] = e1; s[mt][0] += e1;
            float e2 = __expf(d[mt][nt][2] - m[mt][1]); d[mt][nt][2] = e2; s[mt][1] += e2;
            float e3 = __expf(d[mt][nt][3] - m[mt][1]); d[mt][nt][3] = e3; s[mt][1] += e3;
        }
#pragma unroll
    for (int o = 1; o < 4; o <<= 1)
#pragma unroll
        for (int mt = 0; mt < 2; mt++)
#pragma unroll
            for (int rj = 0; rj < 2; rj++)
                s[mt][rj] += __shfl_xor_sync(0xffffffffu, s[mt][rj], o);
    if (q == 0) {
#pragma unroll
        for (int mt = 0; mt < 2; mt++)
#pragma unroll
            for (int rj = 0; rj < 2; rj++)
                rowsum[wkg * 128 + wt + mt * 16 + rj * 8 + ra] = s[mt][rj];
    }
    __syncthreads();
    float inv[2][2];
#pragma unroll
    for (int mt = 0; mt < 2; mt++)
#pragma unroll
        for (int rj = 0; rj < 2; rj++)
            inv[mt][rj] = 1.f / (s[mt][rj] + rowsum[(wkg ^ 1) * 128 + wt + mt * 16 + rj * 8 + ra]);

    float2 ap[4] = {{0,0},{0,0},{0,0},{0,0}};
#pragma unroll
    for (int mt = 0; mt < 2; mt++)
#pragma unroll
        for (int nt = 0; nt < 4; nt++)
#pragma unroll
            for (int rj = 0; rj < 2; rj++) {
                float v0 = d[mt][nt][2 * rj]     * inv[mt][rj];
                float v1 = d[mt][nt][2 * rj + 1] * inv[mt][rj];
                ap[nt].x += v0; ap[nt].y += v1;
                __nv_bfloat162 h, l;
                split_pair(v0, v1, h, l);
                int tl = wt + mt * 16 + rj * 8 + ra;
                int kk = wk + nt * 8 + cb2;
                uint32_t off = (uint32_t)(tl * STRB + kk * 2);
                *(uint32_t*)(sm + E_TH + off) = b2u(h);
                *(uint32_t*)(sm + E_TL + off) = b2u(l);
            }
#pragma unroll
    for (int o = 4; o < 32; o <<= 1)
#pragma unroll
        for (int nt = 0; nt < 4; nt++) {
            ap[nt].x += __shfl_xor_sync(0xffffffffu, ap[nt].x, o);
            ap[nt].y += __shfl_xor_sync(0xffffffffu, ap[nt].y, o);
        }
    if (lane < 4) {
#pragma unroll
        for (int nt = 0; nt < 4; nt++) {
            int kk = wk + nt * 8 + lane * 2;
            sPart[wtg * 64 + kk]     = ap[nt].x;
            sPart[wtg * 64 + kk + 1] = ap[nt].y;
        }
    }
    __syncthreads();
    if (tid < KK) {
        float ssum = sPart[tid] + sPart[64 + tid] + sPart[128 + tid] + sPart[192 + tid];
        g_asumP[(n * 8 + tile) * KK + tid] = ssum;
    }
#pragma unroll
    for (int it = 0; it < 4; it++) {
        int idx = tid + it * 256;
        int t = idx >> 3, seg = idx & 7;
        size_t g = ((size_t)(n * TT + t0 + t)) * KK + seg * 8;
        *(uint4*)&g_aTh[g] = *(uint4*)(sm + E_TH + t * STRB + seg * 16);
        *(uint4*)&g_aTl[g] = *(uint4*)(sm + E_TL + t * STRB + seg * 16);
    }
}

// ---------------------------------------------------------------------------
// kB: vlad[64k x 128c] = sum_t a[t][k]^T x[t][c]; a fragments via ldm4t.
// grid (4, 32), 256 thr; x reg-prefetch, a cp.async 2-buf. (R10 exact)
// ---------------------------------------------------------------------------
__global__ __launch_bounds__(256, 2) void kB(const float* __restrict__ x,
                                             const float* __restrict__ cent,
                                             float* __restrict__ out) {
    extern __shared__ __align__(16) char sm[];
    const int n = blockIdx.y, cb = blockIdx.x, c0 = cb * 128;
    const int tid = threadIdx.x, wid = tid >> 5, lane = tid & 31;
    const int wk = (wid & 1) * 32, wc = (wid >> 1) * 32;
    const uint32_t sbase = smem_u32(sm);
    float* sAux = (float*)(sm + B_AUX);

    float d[2][4][4];
#pragma unroll
    for (int mt = 0; mt < 2; mt++)
#pragma unroll
        for (int nt = 0; nt < 4; nt++)
#pragma unroll
            for (int j = 0; j < 4; j++) d[mt][nt][j] = 0.f;

    const float* xn = x + (size_t)n * TT * CC + c0;
    const __nv_bfloat16* gah = g_aTh + (size_t)n * TT * KK;   // [t][k]
    const __nv_bfloat16* gal = g_aTl + (size_t)n * TT * KK;
    const int xt = tid >> 5, xc4 = tid & 31;
    const int at = tid >> 3, aseg = tid & 7;

    float4 px[8];
#pragma unroll
    for (int it = 0; it < 8; it++)
        px[it] = *(const float4*)(xn + (size_t)(xt + it * 8) * CC + xc4 * 4);
    {
        uint32_t dh = sbase + B_AH0 + at * STRB + aseg * 16;
#pragma unroll
        for (int q2 = 0; q2 < 2; q2++) {
            int tr = at + q2 * 32;
            CPA16(dh + q2 * 32 * STRB, &gah[(size_t)tr * KK + aseg * 8]);
            CPA16(dh + q2 * 32 * STRB + 9216, &gal[(size_t)tr * KK + aseg * 8]);
        }
        CPA_COMMIT();
    }

#pragma unroll 1
    for (int ch = 0; ch < 16; ch++) {
        __syncthreads();
#pragma unroll
        for (int it = 0; it < 8; it++) {
            __nv_bfloat162 h0, l0, h1, l1;
            split_pair(px[it].x, px[it].y, h0, l0);
            split_pair(px[it].z, px[it].w, h1, l1);
            uint32_t off = (uint32_t)((xt + it * 8) * STRB2 + xc4 * 8);
            *(uint2*)(sm + B_XH + off) = make_uint2(b2u(h0), b2u(h1));
            *(uint2*)(sm + B_XL + off) = make_uint2(b2u(l0), b2u(l1));
        }
        if (ch < 15) {
            uint32_t ab = ((ch + 1) & 1) ? B_AH1 : B_AH0;
            uint32_t dh = sbase + ab + at * STRB + aseg * 16;
            int tn = (ch + 1) * 64;
#pragma unroll
            for (int q2 = 0; q2 < 2; q2++) {
                int tr = tn + at + q2 * 32;
                CPA16(dh + q2 * 32 * STRB, &gah[(size_t)tr * KK + aseg * 8]);
                CPA16(dh + q2 * 32 * STRB + 9216, &gal[(size_t)tr * KK + aseg * 8]);
            }
            CPA_COMMIT();
#pragma unroll
            for (int it = 0; it < 8; it++)
                px[it] = *(const float4*)(xn + (size_t)(tn + xt + it * 8) * CC + xc4 * 4);
            CPA_WAIT1();
        } else {
            CPA_WAIT0();
        }
        __syncthreads();

        const uint32_t abase = sbase + ((ch & 1) ? B_AH1 : B_AH0);
#pragma unroll
        for (int ks = 0; ks < 4; ks++) {
            const int ts = ks * 16;
            uint32_t ah[2][4], al[2][4];
#pragma unroll
            for (int mt = 0; mt < 2; mt++) {
                int g = lane >> 3;
                uint32_t a = abase + (uint32_t)((ts + ((g >> 1) << 3) + (lane & 7)) * STRB
                              + (wk + mt * 16 + ((g & 1) << 3)) * 2);
                ldm4t(ah[mt], a);
                ldm4t(al[mt], a + 9216);
            }
            uint32_t bh[4][2], bl[4][2];
#pragma unroll
            for (int p = 0; p < 2; p++) {
                int g = lane >> 3;
                uint32_t a = sbase + B_XH + (uint32_t)((ts + ((g & 1) << 3) + (lane & 7)) * STRB2
                              + (wc + p * 16 + ((g >> 1) << 3)) * 2);
                uint32_t r[4];
                ldm4t(r, a);
                bh[2 * p][0] = r[0]; bh[2 * p][1] = r[1];
                bh[2 * p + 1][0] = r[2]; bh[2 * p + 1][1] = r[3];
                ldm4t(r, a + 17408);
                bl[2 * p][0] = r[0]; bl[2 * p][1] = r[1];
                bl[2 * p + 1][0] = r[2]; bl[2 * p + 1][1] = r[3];
            }
#pragma unroll
            for (int mt = 0; mt < 2; mt++)
#pragma unroll
                for (int nt = 0; nt < 4; nt++) {
                    mma16816(d[mt][nt], ah[mt], bh[nt]);
                    mma16816(d[mt][nt], ah[mt], bl[nt]);
                    mma16816(d[mt][nt], al[mt], bh[nt]);
                }
        }
    }
    __syncthreads();

    float* sC = (float*)(sm + O_SC);
    float* sO = (float*)(sm + O_SO);
    if (tid < KK) {
        float s = 0.f;
#pragma unroll
        for (int j = 0; j < 8; j++) s += g_asumP[(n * 8 + j) * KK + tid];
        sAux[tid] = s;
    }
#pragma unroll
    for (int it = 0; it < 8; it++) {
        int i2 = tid + it * 256;
        int k = i2 >> 5, c4 = i2 & 31;
        *(float4*)&sC[k * 132 + c4 * 4] = *(const float4*)&cent[k * CC + c0 + c4 * 4];
    }
    __syncthreads();

#pragma unroll
    for (int mt = 0; mt < 2; mt++)
#pragma unroll
        for (int nt = 0; nt < 4; nt++) {
            int k = wk + mt * 16 + (lane >> 2);
            int c = wc + nt * 8 + (lane & 3) * 2;
            float as0 = sAux[k], as1 = sAux[k + 8];
            sO[k * 132 + c]           = d[mt][nt][0] - as0 * sC[k * 132 + c];
            sO[k * 132 + c + 1]       = d[mt][nt][1] - as0 * sC[k * 132 + c + 1];
            sO[(k + 8) * 132 + c]     = d[mt][nt][2] - as1 * sC[(k + 8) * 132 + c];
            sO[(k + 8) * 132 + c + 1] = d[mt][nt][3] - as1 * sC[(k + 8) * 132 + c + 1];
        }
    __syncthreads();

    if (tid < KK) {
        float s = 0.f;
#pragma unroll 8
        for (int c = 0; c < 128; c++) { float v = sO[tid * 132 + c]; s = fmaf(v, v, s); }
        g_sqP[(n * 4 + cb) * KK + tid] = s;
    }
#pragma unroll
    for (int it = 0; it < 8; it++) {
        int i2 = tid + it * 256;
        int k = i2 >> 5, c4 = i2 & 31;
        *(float4*)&out[(size_t)(n * KK + k) * CC + c0 + c4 * 4] = *(float4*)&sO[k * 132 + c4 * 4];
    }
}

// ---------------------------------------------------------------------------
// kN: intra + global L2 normalization. grid (32 n, 16 k-chunks of 4), 256 thr.
// ---------------------------------------------------------------------------
__global__ __launch_bounds__(256) void kN(float* __restrict__ out) {
    const int n = blockIdx.x, kc = blockIdx.y;
    const int tid = threadIdx.x;
    __shared__ float sInv[KK];
    __shared__ float sRed[2];
    __shared__ float sG;

    float contrib = 0.f;
    if (tid < KK) {
        float s = 0.f;
#pragma unroll
        for (int j = 0; j < 4; j++) s += g_sqP[(n * 4 + j) * KK + tid];
        float inv = 1.f / fmaxf(sqrtf(s), FEPS);
        sInv[tid] = inv;
        contrib = s * inv * inv;
#pragma unroll
        for (int o = 16; o > 0; o >>= 1) contrib += __shfl_xor_sync(0xffffffffu, contrib, o);
        if ((tid & 31) == 0) sRed[tid >> 5] = contrib;
    }
    __syncthreads();
    if (tid == 0) sG = 1.f / fmaxf(sqrtf(sRed[0] + sRed[1]), FEPS);
    __syncthreads();
    float g = sG;
#pragma unroll
    for (int it = 0; it < 2; it++) {
        int idx = tid + it * 256;
        int kl = idx >> 7, c4 = idx & 127;
        int k = kc * 4 + kl;
        float f = sInv[k] * g;
        float4* p = (float4*)&out[((size_t)n * KK + k) * CC + c4 * 4];
        float4 v = *p;
        v.x *= f; v.y *= f; v.z *= f; v.w *= f;
        *p = v;
    }
}

extern "C" void kernel_launch(void* const* d_in, const int* in_sizes, int n_in,
                              void* d_out, int out_size) {
    const float* x    = (const float*)d_in[0];  // [32,1024,512]
    const float* W    = (const float*)d_in[1];  // [64,512]
    const float* b    = (const float*)d_in[2];  // [64]
    const float* cent = (const float*)d_in[3];  // [64,512]
    float* out = (float*)d_out;

    cudaFuncSetAttribute(kA, cudaFuncAttributeMaxDynamicSharedMemorySize, SMEM_A);
    cudaFuncSetAttribute(kB, cudaFuncAttributeMaxDynamicSharedMemorySize, SMEM_B);

    kW<<<64, 128>>>(W);
    kA<<<dim3(8, NB), 256, SMEM_A>>>(x, b);
    kB<<<dim3(4, NB), 256, SMEM_B>>>(x, cent, out);
    kN<<<dim3(NB, 16), 256>>>(out);
}

// round 17
// speedup vs baseline: 1.5246x; 1.5246x over previous
#include <cuda_runtime.h>
#include <cuda_bf16.h>
#include <stdint.h>
#include <math.h>

#define NB 32
#define TT 1024
#define CC 512
#define KK 64
#define FEPS 1e-12f

#define STRB 144      // 64-col operand row stride bytes (36 words == 4 mod 32)
#define STRB2 272     // 128-col operand row stride bytes (68 words == 4 mod 32)

// kA smem (bytes) — R4 mainloop layout
#define A_XH 0                // 128 x 144 = 18432
#define A_XL 18432            // ends 36864
#define A_WH0 36864           // 64 x 144 = 9216
#define A_WL0 46080
#define A_WH1 55296
#define A_WL1 64512           // ends 73728
#define A_AUX 73728
#define SMEM_A 73984
// kA epilogue overlay (post-mainloop-sync reuse)
#define E_TH 0                // a hi bf16 [128 t][144B]
#define E_TL 18432            // a lo
#define E_RM 36864            // rowmax [2][128] f32 = 1024
#define E_RS 37888            // rowsum [2][128] f32 = 1024
#define E_PART 38912          // asum partials [4][64] f32 = 1024

// kB smem — R4 layout (a [t][k], tile 64x64)
#define B_XH 0                // 64 x 272 = 17408
#define B_XL 17408            // ends 34816
#define B_AH0 34816           // 64 x 144 = 9216
#define B_AL0 44032
#define B_AH1 53248
#define B_AL1 62464           // ends 71680
#define B_AUX 71680
#define SMEM_B 71936
#define O_SC 0                // 64 x 132 f32
#define O_SO 33792            // ends 67584

// ---- scratch ----
__device__ __align__(16) __nv_bfloat16 g_aTh[(size_t)NB * TT * KK];  // [n][t][k] hi
__device__ __align__(16) __nv_bfloat16 g_aTl[(size_t)NB * TT * KK];  // [n][t][k] lo
__device__ __align__(16) __nv_bfloat16 g_Wh[KK * CC];
__device__ __align__(16) __nv_bfloat16 g_Wl[KK * CC];
__device__ float g_asumP[NB * 8 * KK];
__device__ float g_sqP[NB * 4 * KK];

__device__ __forceinline__ uint32_t smem_u32(const void* p) {
    uint32_t a;
    asm("{ .reg .u64 t; cvta.to.shared.u64 t, %1; cvt.u32.u64 %0, t; }" : "=r"(a) : "l"(p));
    return a;
}
__device__ __forceinline__ uint32_t b2u(__nv_bfloat162 v) { return *reinterpret_cast<uint32_t*>(&v); }
__device__ __forceinline__ void split_pair(float f0, float f1, __nv_bfloat162& h, __nv_bfloat162& l) {
    h = __floats2bfloat162_rn(f0, f1);
    float2 hf = __bfloat1622float2(h);
    l = __floats2bfloat162_rn(f0 - hf.x, f1 - hf.y);
}
__device__ __forceinline__ void mma16816(float* d, const uint32_t* a, const uint32_t* b) {
    asm volatile("mma.sync.aligned.m16n8k16.row.col.f32.bf16.bf16.f32 "
                 "{%0,%1,%2,%3}, {%4,%5,%6,%7}, {%8,%9}, {%0,%1,%2,%3};"
                 : "+f"(d[0]), "+f"(d[1]), "+f"(d[2]), "+f"(d[3])
                 : "r"(a[0]), "r"(a[1]), "r"(a[2]), "r"(a[3]), "r"(b[0]), "r"(b[1]));
}
__device__ __forceinline__ void ldm4(uint32_t* r, uint32_t a) {
    asm volatile("ldmatrix.sync.aligned.m8n8.x4.shared.b16 {%0,%1,%2,%3}, [%4];"
                 : "=r"(r[0]), "=r"(r[1]), "=r"(r[2]), "=r"(r[3]) : "r"(a));
}
__device__ __forceinline__ void ldm4t(uint32_t* r, uint32_t a) {
    asm volatile("ldmatrix.sync.aligned.m8n8.x4.trans.shared.b16 {%0,%1,%2,%3}, [%4];"
                 : "=r"(r[0]), "=r"(r[1]), "=r"(r[2]), "=r"(r[3]) : "r"(a));
}
#define CPA16(dst, src) asm volatile("cp.async.ca.shared.global [%0], [%1], 16;" :: "r"(dst), "l"(src))
#define CPA_COMMIT() asm volatile("cp.async.commit_group;")
#define CPA_WAIT1() asm volatile("cp.async.wait_group 1;")
#define CPA_WAIT0() asm volatile("cp.async.wait_group 0;")

// ---------------------------------------------------------------------------
__global__ void kW(const float* __restrict__ W) {
    int i = blockIdx.x * 512 + threadIdx.x;
    if (i < KK * CC) {
        float v = W[i];
        __nv_bfloat16 h = __float2bfloat16(v);
        g_Wh[i] = h;
        g_Wl[i] = __float2bfloat16(v - __bfloat162float(h));
    }
}

// ---------------------------------------------------------------------------
// kA: logits[128t x 64k] = x @ W^T + bias, softmax -> a bf16 [n][t][k]
// Mainloop = R4 (measured best). Register-resident epilogue.
// ---------------------------------------------------------------------------
__global__ __launch_bounds__(256, 2) void kA(const float* __restrict__ x,
                                             const float* __restrict__ b) {
    extern __shared__ __align__(16) char sm[];
    const int tid = threadIdx.x, wid = tid >> 5, lane = tid & 31;
    const int n = blockIdx.y, tile = blockIdx.x, t0 = tile * 128;
    const int wt = (wid & 3) * 32, wk = (wid >> 2) * 32;
    const uint32_t sbase = smem_u32(sm);
    float* sAux = (float*)(sm + A_AUX);
    if (tid < KK) sAux[tid] = b[tid];

    float d[2][4][4];
#pragma unroll
    for (int mt = 0; mt < 2; mt++)
#pragma unroll
        for (int nt = 0; nt < 4; nt++)
#pragma unroll
            for (int j = 0; j < 4; j++) d[mt][nt][j] = 0.f;

    const float* xn = x + ((size_t)n * TT + t0) * CC;
    const int xt = tid >> 4, xc4 = tid & 15;
    const int wk8 = tid >> 3, wseg = tid & 7;

    float4 px[8];
#pragma unroll
    for (int it = 0; it < 8; it++)
        px[it] = *(const float4*)(xn + (size_t)(xt + it * 16) * CC + xc4 * 4);
    {   // W(0)
        uint32_t dh = sbase + A_WH0 + wk8 * STRB + wseg * 16;
#pragma unroll
        for (int q2 = 0; q2 < 2; q2++) {
            int k = wk8 + q2 * 32;
            CPA16(dh + q2 * 32 * STRB, &g_Wh[k * CC + wseg * 8]);
            CPA16(dh + q2 * 32 * STRB + 9216, &g_Wl[k * CC + wseg * 8]);
        }
        CPA_COMMIT();
    }

#pragma unroll 1
    for (int ch = 0; ch < 8; ch++) {
        __syncthreads();
#pragma unroll
        for (int it = 0; it < 8; it++) {
            __nv_bfloat162 h0, l0, h1, l1;
            split_pair(px[it].x, px[it].y, h0, l0);
            split_pair(px[it].z, px[it].w, h1, l1);
            uint32_t off = (uint32_t)((xt + it * 16) * STRB + xc4 * 8);
            *(uint2*)(sm + A_XH + off) = make_uint2(b2u(h0), b2u(h1));
            *(uint2*)(sm + A_XL + off) = make_uint2(b2u(l0), b2u(l1));
        }
        if (ch < 7) {
            uint32_t wb = ((ch + 1) & 1) ? A_WH1 : A_WH0;
            uint32_t dh = sbase + wb + wk8 * STRB + wseg * 16;
            int cn = (ch + 1) * 64;
#pragma unroll
            for (int q2 = 0; q2 < 2; q2++) {
                int k = wk8 + q2 * 32;
                CPA16(dh + q2 * 32 * STRB, &g_Wh[k * CC + cn + wseg * 8]);
                CPA16(dh + q2 * 32 * STRB + 9216, &g_Wl[k * CC + cn + wseg * 8]);
            }
            CPA_COMMIT();
#pragma unroll
            for (int it = 0; it < 8; it++)
                px[it] = *(const float4*)(xn + (size_t)(xt + it * 16) * CC + cn + xc4 * 4);
            CPA_WAIT1();
        } else {
            CPA_WAIT0();
        }
        __syncthreads();

        const uint32_t wbase = sbase + ((ch & 1) ? A_WH1 : A_WH0);
#pragma unroll
        for (int ks = 0; ks < 4; ks++) {
            const int cs = ks * 16;
            uint32_t ah[2][4], al[2][4];
#pragma unroll
            for (int mt = 0; mt < 2; mt++) {
                uint32_t a = sbase + A_XH + (uint32_t)((wt + mt * 16 + (lane & 15)) * STRB
                              + (cs + ((lane >> 4) << 3)) * 2);
                ldm4(ah[mt], a);
                ldm4(al[mt], a + 18432);
            }
            uint32_t bh[4][2], bl[4][2];
#pragma unroll
            for (int p = 0; p < 2; p++) {
                int g = lane >> 3;
                uint32_t a = wbase + (uint32_t)((wk + p * 16 + ((g >> 1) << 3) + (lane & 7)) * STRB
                              + (cs + ((g & 1) << 3)) * 2);
                uint32_t r[4];
                ldm4(r, a);
                bh[2 * p][0] = r[0]; bh[2 * p][1] = r[1];
                bh[2 * p + 1][0] = r[2]; bh[2 * p + 1][1] = r[3];
                ldm4(r, a + 9216);
                bl[2 * p][0] = r[0]; bl[2 * p][1] = r[1];
                bl[2 * p + 1][0] = r[2]; bl[2 * p + 1][1] = r[3];
            }
#pragma unroll
            for (int mt = 0; mt < 2; mt++)
#pragma unroll
                for (int nt = 0; nt < 4; nt++) {
                    mma16816(d[mt][nt], ah[mt], bh[nt]);
                    mma16816(d[mt][nt], ah[mt], bl[nt]);
                    mma16816(d[mt][nt], al[mt], bh[nt]);
                }
        }
    }
    __syncthreads();   // all warps done with X/W smem

    // ===== register-resident epilogue =====
    const int ra = lane >> 2, q = lane & 3, cb2 = q * 2;
    const int wtg = wid & 3, wkg = wid >> 2;
    float* rowmax = (float*)(sm + E_RM);
    float* rowsum = (float*)(sm + E_RS);
    float* sPart  = (float*)(sm + E_PART);

    // bias add
    float2 bb[4];
#pragma unroll
    for (int nt = 0; nt < 4; nt++) bb[nt] = *(float2*)&sAux[wk + nt * 8 + cb2];
#pragma unroll
    for (int mt = 0; mt < 2; mt++)
#pragma unroll
        for (int nt = 0; nt < 4; nt++) {
            d[mt][nt][0] += bb[nt].x; d[mt][nt][1] += bb[nt].y;
            d[mt][nt][2] += bb[nt].x; d[mt][nt][3] += bb[nt].y;
        }

    // per-row max over this warp's 32 k's
    float m[2][2];
#pragma unroll
    for (int mt = 0; mt < 2; mt++) {
        m[mt][0] = -1e30f; m[mt][1] = -1e30f;
#pragma unroll
        for (int nt = 0; nt < 4; nt++) {
            m[mt][0] = fmaxf(m[mt][0], fmaxf(d[mt][nt][0], d[mt][nt][1]));
            m[mt][1] = fmaxf(m[mt][1], fmaxf(d[mt][nt][2], d[mt][nt][3]));
        }
    }
#pragma unroll
    for (int o = 1; o < 4; o <<= 1)
#pragma unroll
        for (int mt = 0; mt < 2; mt++)
#pragma unroll
            for (int rj = 0; rj < 2; rj++)
                m[mt][rj] = fmaxf(m[mt][rj], __shfl_xor_sync(0xffffffffu, m[mt][rj], o));
    if (q == 0) {
#pragma unroll
        for (int mt = 0; mt < 2; mt++)
#pragma unroll
            for (int rj = 0; rj < 2; rj++)
                rowmax[wkg * 128 + wt + mt * 16 + rj * 8 + ra] = m[mt][rj];
    }
    __syncthreads();
#pragma unroll
    for (int mt = 0; mt < 2; mt++)
#pragma unroll
        for (int rj = 0; rj < 2; rj++)
            m[mt][rj] = fmaxf(m[mt][rj], rowmax[(wkg ^ 1) * 128 + wt + mt * 16 + rj * 8 + ra]);

    // exp + per-row sum (this warp's 32 k's)
    float s[2][2] = {{0.f, 0.f}, {0.f, 0.f}};
#pragma unroll
    for (int mt = 0; mt < 2; mt++)
#pragma unroll
        for (int nt = 0; nt < 4; nt++) {
            float e0 = __expf(d[mt][nt][0] - m[mt][0]); d[mt][nt][0] = e0; s[mt][0] += e0;
            float e1 = __expf(d[mt][nt][1] - m[mt][0]); d[mt][nt][1] = e1; s[mt][0] += e1;
            float e2 = __expf(d[mt][nt][2] - m[mt][1]); d[mt][nt][2] = e2; s[mt][1] += e2;
            float e3 = __expf(d[mt][nt][3] - m[mt][1]); d[mt][nt][3] = e3; s[mt][1] += e3;
        }
#pragma unroll
    for (int o = 1; o < 4; o <<= 1)
#pragma unroll
        for (int mt = 0; mt < 2; mt++)
#pragma unroll
            for (int rj = 0; rj < 2; rj++)
                s[mt][rj] += __shfl_xor_sync(0xffffffffu, s[mt][rj], o);
    if (q == 0) {
#pragma unroll
        for (int mt = 0; mt < 2; mt++)
#pragma unroll
            for (int rj = 0; rj < 2; rj++)
                rowsum[wkg * 128 + wt + mt * 16 + rj * 8 + ra] = s[mt][rj];
    }
    __syncthreads();
    float inv[2][2];
#pragma unroll
    for (int mt = 0; mt < 2; mt++)
#pragma unroll
        for (int rj = 0; rj < 2; rj++)
            inv[mt][rj] = 1.f / (s[mt][rj] + rowsum[(wkg ^ 1) * 128 + wt + mt * 16 + rj * 8 + ra]);

    // normalize, split, STS [t][k], accumulate asum partials
    float2 ap[4] = {{0,0},{0,0},{0,0},{0,0}};
#pragma unroll
    for (int mt = 0; mt < 2; mt++)
#pragma unroll
        for (int nt = 0; nt < 4; nt++)
#pragma unroll
            for (int rj = 0; rj < 2; rj++) {
                float v0 = d[mt][nt][2 * rj]     * inv[mt][rj];
                float v1 = d[mt][nt][2 * rj + 1] * inv[mt][rj];
                ap[nt].x += v0; ap[nt].y += v1;
                __nv_bfloat162 h, l;
                split_pair(v0, v1, h, l);
                int tl = wt + mt * 16 + rj * 8 + ra;
                int kk = wk + nt * 8 + cb2;
                uint32_t off = (uint32_t)(tl * STRB + kk * 2);
                *(uint32_t*)(sm + E_TH + off) = b2u(h);
                *(uint32_t*)(sm + E_TL + off) = b2u(l);
            }
#pragma unroll
    for (int o = 4; o < 32; o <<= 1)
#pragma unroll
        for (int nt = 0; nt < 4; nt++) {
            ap[nt].x += __shfl_xor_sync(0xffffffffu, ap[nt].x, o);
            ap[nt].y += __shfl_xor_sync(0xffffffffu, ap[nt].y, o);
        }
    if (lane < 4) {
#pragma unroll
        for (int nt = 0; nt < 4; nt++) {
            int kk = wk + nt * 8 + lane * 2;
            sPart[wtg * 64 + kk]     = ap[nt].x;
            sPart[wtg * 64 + kk + 1] = ap[nt].y;
        }
    }
    __syncthreads();
    if (tid < KK) {
        float ssum = sPart[tid] + sPart[64 + tid] + sPart[128 + tid] + sPart[192 + tid];
        g_asumP[(n * 8 + tile) * KK + tid] = ssum;
    }
    // coalesced copy-out: a hi/lo [n][t][k]
#pragma unroll
    for (int it = 0; it < 4; it++) {
        int idx = tid + it * 256;
        int t = idx >> 3, seg = idx & 7;
        size_t g = ((size_t)(n * TT + t0 + t)) * KK + seg * 8;
        *(uint4*)&g_aTh[g] = *(uint4*)(sm + E_TH + t * STRB + seg * 16);
        *(uint4*)&g_aTl[g] = *(uint4*)(sm + E_TL + t * STRB + seg * 16);
    }
}

// ---------------------------------------------------------------------------
// kB: vlad[64k x 128c] = sum_t a[t][k]^T x[t][c]; a fragments via ldm4t.
// grid (4, 32), 256 thr; x reg-prefetch, a cp.async 2-buf.
// ---------------------------------------------------------------------------
__global__ __launch_bounds__(256, 2) void kB(const float* __restrict__ x,
                                             const float* __restrict__ cent,
                                             float* __restrict__ out) {
    extern __shared__ __align__(16) char sm[];
    const int n = blockIdx.y, cb = blockIdx.x, c0 = cb * 128;
    const int tid = threadIdx.x, wid = tid >> 5, lane = tid & 31;
    const int wk = (wid & 1) * 32, wc = (wid >> 1) * 32;
    const uint32_t sbase = smem_u32(sm);
    float* sAux = (float*)(sm + B_AUX);

    float d[2][4][4];
#pragma unroll
    for (int mt = 0; mt < 2; mt++)
#pragma unroll
        for (int nt = 0; nt < 4; nt++)
#pragma unroll
            for (int j = 0; j < 4; j++) d[mt][nt][j] = 0.f;

    const float* xn = x + (size_t)n * TT * CC + c0;
    const __nv_bfloat16* gah = g_aTh + (size_t)n * TT * KK;   // [t][k]
    const __nv_bfloat16* gal = g_aTl + (size_t)n * TT * KK;
    const int xt = tid >> 5, xc4 = tid & 31;
    const int at = tid >> 3, aseg = tid & 7;   // a copy: row t, 16B segment

    float4 px[8];
#pragma unroll
    for (int it = 0; it < 8; it++)
        px[it] = *(const float4*)(xn + (size_t)(xt + it * 8) * CC + xc4 * 4);
    {
        uint32_t dh = sbase + B_AH0 + at * STRB + aseg * 16;
#pragma unroll
        for (int q2 = 0; q2 < 2; q2++) {
            int tr = at + q2 * 32;
            CPA16(dh + q2 * 32 * STRB, &gah[(size_t)tr * KK + aseg * 8]);
            CPA16(dh + q2 * 32 * STRB + 9216, &gal[(size_t)tr * KK + aseg * 8]);
        }
        CPA_COMMIT();
    }

#pragma unroll 1
    for (int ch = 0; ch < 16; ch++) {
        __syncthreads();
#pragma unroll
        for (int it = 0; it < 8; it++) {
            __nv_bfloat162 h0, l0, h1, l1;
            split_pair(px[it].x, px[it].y, h0, l0);
            split_pair(px[it].z, px[it].w, h1, l1);
            uint32_t off = (uint32_t)((xt + it * 8) * STRB2 + xc4 * 8);
            *(uint2*)(sm + B_XH + off) = make_uint2(b2u(h0), b2u(h1));
            *(uint2*)(sm + B_XL + off) = make_uint2(b2u(l0), b2u(l1));
        }
        if (ch < 15) {
            uint32_t ab = ((ch + 1) & 1) ? B_AH1 : B_AH0;
            uint32_t dh = sbase + ab + at * STRB + aseg * 16;
            int tn = (ch + 1) * 64;
#pragma unroll
            for (int q2 = 0; q2 < 2; q2++) {
                int tr = tn + at + q2 * 32;
                CPA16(dh + q2 * 32 * STRB, &gah[(size_t)tr * KK + aseg * 8]);
                CPA16(dh + q2 * 32 * STRB + 9216, &gal[(size_t)tr * KK + aseg * 8]);
            }
            CPA_COMMIT();
#pragma unroll
            for (int it = 0; it < 8; it++)
                px[it] = *(const float4*)(xn + (size_t)(tn + xt + it * 8) * CC + xc4 * 4);
            CPA_WAIT1();
        } else {
            CPA_WAIT0();
        }
        __syncthreads();

        const uint32_t abase = sbase + ((ch & 1) ? B_AH1 : B_AH0);
#pragma unroll
        for (int ks = 0; ks < 4; ks++) {
            const int ts = ks * 16;
            uint32_t ah[2][4], al[2][4];
#pragma unroll
            for (int mt = 0; mt < 2; mt++) {
                int g = lane >> 3;
                uint32_t a = abase + (uint32_t)((ts + ((g >> 1) << 3) + (lane & 7)) * STRB
                              + (wk + mt * 16 + ((g & 1) << 3)) * 2);
                ldm4t(ah[mt], a);
                ldm4t(al[mt], a + 9216);
            }
            uint32_t bh[4][2], bl[4][2];
#pragma unroll
            for (int p = 0; p < 2; p++) {
                int g = lane >> 3;
                uint32_t a = sbase + B_XH + (uint32_t)((ts + ((g & 1) << 3) + (lane & 7)) * STRB2
                              + (wc + p * 16 + ((g >> 1) << 3)) * 2);
                uint32_t r[4];
                ldm4t(r, a);
                bh[2 * p][0] = r[0]; bh[2 * p][1] = r[1];
                bh[2 * p + 1][0] = r[2]; bh[2 * p + 1][1] = r[3];
                ldm4t(r, a + 17408);
                bl[2 * p][0] = r[0]; bl[2 * p][1] = r[1];
                bl[2 * p + 1][0] = r[2]; bl[2 * p + 1][1] = r[3];
            }
#pragma unroll
            for (int mt = 0; mt < 2; mt++)
#pragma unroll
                for (int nt = 0; nt < 4; nt++) {
                    mma16816(d[mt][nt], ah[mt], bh[nt]);
                    mma16816(d[mt][nt], ah[mt], bl[nt]);
                    mma16816(d[mt][nt], al[mt], bh[nt]);
                }
        }
    }
    __syncthreads();

    float* sC = (float*)(sm + O_SC);
    float* sO = (float*)(sm + O_SO);
    if (tid < KK) {
        float s = 0.f;
#pragma unroll
        for (int j = 0; j < 8; j++) s += g_asumP[(n * 8 + j) * KK + tid];
        sAux[tid] = s;
    }
#pragma unroll
    for (int it = 0; it < 8; it++) {
        int i2 = tid + it * 256;
        int k = i2 >> 5, c4 = i2 & 31;
        *(float4*)&sC[k * 132 + c4 * 4] = *(const float4*)&cent[k * CC + c0 + c4 * 4];
    }
    __syncthreads();

#pragma unroll
    for (int mt = 0; mt < 2; mt++)
#pragma unroll
        for (int nt = 0; nt < 4; nt++) {
            int k = wk + mt * 16 + (lane >> 2);
            int c = wc + nt * 8 + (lane & 3) * 2;
            float as0 = sAux[k], as1 = sAux[k + 8];
            sO[k * 132 + c]           = d[mt][nt][0] - as0 * sC[k * 132 + c];
            sO[k * 132 + c + 1]       = d[mt][nt][1] - as0 * sC[k * 132 + c + 1];
            sO[(k + 8) * 132 + c]     = d[mt][nt][2] - as1 * sC[(k + 8) * 132 + c];
            sO[(k + 8) * 132 + c + 1] = d[mt][nt][3] - as1 * sC[(k + 8) * 132 + c + 1];
        }
    __syncthreads();

    if (tid < KK) {
        float s = 0.f;
#pragma unroll 8
        for (int c = 0; c < 128; c++) { float v = sO[tid * 132 + c]; s = fmaf(v, v, s); }
        g_sqP[(n * 4 + cb) * KK + tid] = s;
    }
#pragma unroll
    for (int it = 0; it < 8; it++) {
        int i2 = tid + it * 256;
        int k = i2 >> 5, c4 = i2 & 31;
        *(float4*)&out[(size_t)(n * KK + k) * CC + c0 + c4 * 4] = *(float4*)&sO[k * 132 + c4 * 4];
    }
}

// ---------------------------------------------------------------------------
__global__ __launch_bounds__(256) void kN(float* __restrict__ out) {
    const int n = blockIdx.x, kc = blockIdx.y;
    const int tid = threadIdx.x;
    __shared__ float sInv[KK];
    __shared__ float sRed[2];
    __shared__ float sG;

    float contrib = 0.f;
    if (tid < KK) {
        float s = 0.f;
#pragma unroll
        for (int j = 0; j < 4; j++) s += g_sqP[(n * 4 + j) * KK + tid];
        float inv = 1.f / fmaxf(sqrtf(s), FEPS);
        sInv[tid] = inv;
        contrib = s * inv * inv;
#pragma unroll
        for (int o = 16; o > 0; o >>= 1) contrib += __shfl_xor_sync(0xffffffffu, contrib, o);
        if ((tid & 31) == 0) sRed[tid >> 5] = contrib;
    }
    __syncthreads();
    if (tid == 0) sG = 1.f / fmaxf(sqrtf(sRed[0] + sRed[1]), FEPS);
    __syncthreads();
    float g = sG;
#pragma unroll
    for (int it = 0; it < 4; it++) {
        int idx = tid + it * 256;
        int kl = idx >> 7, c4 = idx & 127;
        int k = kc * 8 + kl;
        float f = sInv[k] * g;
        float4* p = (float4*)&out[((size_t)n * KK + k) * CC + c4 * 4];
        float4 v = *p;
        v.x *= f; v.y *= f; v.z *= f; v.w *= f;
        *p = v;
    }
}

extern "C" void kernel_launch(void* const* d_in, const int* in_sizes, int n_in,
                              void* d_out, int out_size) {
    const float* x    = (const float*)d_in[0];  // [32,1024,512]
    const float* W    = (const float*)d_in[1];  // [64,512]
    const float* b    = (const float*)d_in[2];  // [64]
    const float* cent = (const float*)d_in[3];  // [64,512]
    float* out = (float*)d_out;

    cudaFuncSetAttribute(kA, cudaFuncAttributeMaxDynamicSharedMemorySize, SMEM_A);
    cudaFuncSetAttribute(kB, cudaFuncAttributeMaxDynamicSharedMemorySize, SMEM_B);

    kW<<<64, 512>>>(W);
    kA<<<dim3(8, NB), 256, SMEM_A>>>(x, b);
    kB<<<dim3(4, NB), 256, SMEM_B>>>(x, cent, out);
    kN<<<dim3(NB, 8), 256>>>(out);
}